// round 7
// baseline (speedup 1.0000x reference)
#include <cuda_runtime.h>

// DimeNetPP radius-graph distances + triplet angles.
// Inputs: [0] atomic_ns (unused), [1] coords f32 [N,3], [2] batch_node_vec (unused)
// Output: f32, dists [B,48,48] then angles [B,48,48,48].
//
// One warp per (molecule, center-row j). Warps are fully independent after a
// single coords-sharing barrier: adjacency, dists row, zero-fill of the row's
// 48x48 angle slab, and triplet scatter are all warp-local.

#define MOL_B 128
#define MM 48
#define WARPS 4                  // rows per CTA (one per warp)
#define THREADS (WARPS * 32)
#define CTAS (MOL_B * MM / WARPS)   // 1536
#define CUTOFF_F 1.5f

// Branch-free atan2 for y >= 0, (x,y) != (0,0). Max rel err ~1.3e-4.
__device__ __forceinline__ float fast_atan2_pos(float y, float x)
{
    const float ax = fabsf(x);
    const float mn = fminf(y, ax);
    const float mx = fmaxf(y, ax);
    const float t  = __fdividef(mn, mx);
    const float s  = t * t;
    float p = fmaf(s, 0.0208351f, -0.0851330f);
    p = fmaf(s, p, 0.1801410f);
    p = fmaf(s, p, -0.3302995f);
    p = fmaf(s, p, 0.9998660f);
    p = p * t;
    p = (y > ax) ? (1.57079632679f - p) : p;
    p = (x < 0.0f) ? (3.14159265359f - p) : p;
    return p;
}

__global__ __launch_bounds__(THREADS)
void dimenet_kernel(const float* __restrict__ coords, float* __restrict__ out)
{
    const int b    = blockIdx.x / (MM / WARPS);           // molecule
    const int tid  = threadIdx.x;
    const int wid  = tid >> 5;
    const int lane = tid & 31;
    const int j    = (blockIdx.x % (MM / WARPS)) * WARPS + wid;  // center row

    __shared__ float cs[MM * 3];
    __shared__ float nx[WARPS][MM], ny[WARPS][MM], nz[WARPS][MM], nd2[WARPS][MM];
    __shared__ int   nk[WARPS][MM];

    // Load molecule coords (144 floats).
    for (int e = tid; e < MM * 3; e += THREADS) cs[e] = coords[b * (MM * 3) + e];

    float* __restrict__ dists  = out;
    float* __restrict__ angles = out + (size_t)MOL_B * MM * MM;

    // Zero-fill this warp's 48x48 angle slab while the coords LDG is in flight.
    float* const rowbase = angles + (((size_t)b * MM + j) * MM) * MM;
    {
        float4* zb = reinterpret_cast<float4*>(rowbase);
        const float4 z = make_float4(0.f, 0.f, 0.f, 0.f);
        #pragma unroll
        for (int t = 0; t < MM * MM / 4 / 32; t++)        // 18 per lane
            zb[lane + t * 32] = z;
    }
    __syncthreads();   // coords visible; the ONLY block barrier.

    // Phase 1: adjacency + dists row + compacted neighbor vectors (warp-local).
    const float px = cs[j * 3 + 0], py = cs[j * 3 + 1], pz = cs[j * 3 + 2];
    const unsigned below = (1u << lane) - 1u;
    float* const drow = dists + ((size_t)b * MM + j) * MM;

    // chunk 0: q = lane
    const int q0 = lane;
    const float vx0 = cs[q0 * 3 + 0] - px;
    const float vy0 = cs[q0 * 3 + 1] - py;
    const float vz0 = cs[q0 * 3 + 2] - pz;
    const float d20 = vx0 * vx0 + vy0 * vy0 + vz0 * vz0;
    const float dist0 = sqrtf(d20);
    const bool adj0 = (q0 != j) && (dist0 < CUTOFF_F);
    drow[q0] = adj0 ? dist0 : 0.0f;
    const unsigned m0 = __ballot_sync(0xffffffffu, adj0);

    // chunk 1: q = lane + 32 (lanes 0..15)
    bool adj1 = false;
    const int q1 = lane + 32;
    float vx1 = 0.f, vy1 = 0.f, vz1 = 0.f, d21 = 0.f;
    if (lane < 16) {
        vx1 = cs[q1 * 3 + 0] - px;
        vy1 = cs[q1 * 3 + 1] - py;
        vz1 = cs[q1 * 3 + 2] - pz;
        d21 = vx1 * vx1 + vy1 * vy1 + vz1 * vz1;
        const float dist1 = sqrtf(d21);
        adj1 = (q1 != j) && (dist1 < CUTOFF_F);
        drow[q1] = adj1 ? dist1 : 0.0f;
    }
    const unsigned m1 = __ballot_sync(0xffffffffu, adj1);

    const int c0 = __popc(m0);
    const int c  = c0 + __popc(m1);        // neighbor count, known to all lanes
    if (adj0) {
        const int s = __popc(m0 & below);
        nx[wid][s] = vx0; ny[wid][s] = vy0; nz[wid][s] = vz0;
        nd2[wid][s] = d20; nk[wid][s] = q0;
    }
    if (adj1) {
        const int s = c0 + __popc(m1 & below);
        nx[wid][s] = vx1; ny[wid][s] = vy1; nz[wid][s] = vz1;
        nd2[wid][s] = d21; nk[wid][s] = q1;
    }
    __syncwarp();

    // Phase 2: triplets for this row (~c^2 ≈ 121), warp-strided.
    const int T = c * c;
    const float fc = (float)c;
    #pragma unroll 4
    for (int g = lane; g < T; g += 32) {
        const int pi = (int)__fdividef((float)g + 0.5f, fc);
        const int ki = g - pi * c;

        const float vix = nx[wid][pi], viy = ny[wid][pi], viz = nz[wid][pi];
        const float vkx = nx[wid][ki], vky = ny[wid][ki], vkz = nz[wid][ki];
        const float a  = vix * vkx + viy * vky + viz * vkz;
        const float b2 = fmaxf(nd2[wid][pi] * nd2[wid][ki] - a * a, 0.f);
        const float ang = fast_atan2_pos(sqrtf(b2), a);

        if (pi != ki)
            rowbase[nk[wid][pi] * MM + nk[wid][ki]] = ang;
    }
}

extern "C" void kernel_launch(void* const* d_in, const int* in_sizes, int n_in,
                              void* d_out, int out_size)
{
    const float* coords = (const float*)d_in[1];
    float* out = (float*)d_out;
    dimenet_kernel<<<CTAS, THREADS>>>(coords, out);
}

// round 8
// speedup vs baseline: 1.1345x; 1.1345x over previous
#include <cuda_runtime.h>

// DimeNetPP radius-graph distances + triplet angles.
// Inputs: [0] atomic_ns (unused), [1] coords f32 [N,3], [2] batch_node_vec (unused)
// Output: f32, dists [B,48,48] then angles [B,48,48,48].
//
// CTA = 4 warps = 2 center rows; each row is owned by a PAIR of warps:
//   half 0: zero-fill half the row's 48x48 slab + adjacency + dists row
//   half 1: zero-fill the other half
//   (one __syncthreads)  then both halves scatter interleaved triplets.
// Grid 3072 -> ~21 CTAs/SM offered: fills the SM to its reg-limited warp
// capacity and leaves a backfill wave to cover the drain tail.

#define MOL_B 128
#define MM 48
#define THREADS 128
#define CTAS (MOL_B * MM / 2)    // 3072, 2 rows per CTA
#define CUTOFF_F 1.5f

// Branch-free atan2 for y >= 0, (x,y) != (0,0). Max rel err ~1.3e-4.
__device__ __forceinline__ float fast_atan2_pos(float y, float x)
{
    const float ax = fabsf(x);
    const float mn = fminf(y, ax);
    const float mx = fmaxf(y, ax);
    const float t  = __fdividef(mn, mx);
    const float s  = t * t;
    float p = fmaf(s, 0.0208351f, -0.0851330f);
    p = fmaf(s, p, 0.1801410f);
    p = fmaf(s, p, -0.3302995f);
    p = fmaf(s, p, 0.9998660f);
    p = p * t;
    p = (y > ax) ? (1.57079632679f - p) : p;
    p = (x < 0.0f) ? (3.14159265359f - p) : p;
    return p;
}

__global__ __launch_bounds__(THREADS)
void dimenet_kernel(const float* __restrict__ coords, float* __restrict__ out)
{
    const int cta  = blockIdx.x;
    const int b    = cta / (MM / 2);                 // molecule
    const int pair = cta % (MM / 2);                 // row-pair index
    const int tid  = threadIdx.x;
    const int wid  = tid >> 5;
    const int lane = tid & 31;
    const int rl   = wid >> 1;                       // local row 0/1
    const int half = wid & 1;                        // warp half within the pair
    const int j    = pair * 2 + rl;                  // center row

    __shared__ float cs[MM * 3];
    __shared__ float nx[2][MM], ny[2][MM], nz[2][MM], nd2[2][MM];
    __shared__ int   nk[2][MM];
    __shared__ int   cnts[2];

    // Coords: 144 floats = 36 float4.
    if (tid < MM * 3 / 4)
        reinterpret_cast<float4*>(cs)[tid] =
            reinterpret_cast<const float4*>(coords + b * (MM * 3))[tid];

    float* __restrict__ dists  = out;
    float* __restrict__ angles = out + (size_t)MOL_B * MM * MM;

    // Zero-fill: each warp covers half of its row's 2304-float slab (288 f4).
    float* const rowbase = angles + (((size_t)b * MM + j) * MM) * MM;
    {
        float4* zb = reinterpret_cast<float4*>(rowbase) + half * 288;
        const float4 z = make_float4(0.f, 0.f, 0.f, 0.f);
        #pragma unroll
        for (int t = 0; t < 9; t++)
            zb[lane + t * 32] = z;
    }
    __syncthreads();   // coords visible (also part of fill ordering)

    // Phase 1 (half 0 only): adjacency, dists row, compacted neighbor data.
    if (half == 0) {
        const float px = cs[j * 3 + 0], py = cs[j * 3 + 1], pz = cs[j * 3 + 2];
        const unsigned below = (1u << lane) - 1u;
        float* const drow = dists + ((size_t)b * MM + j) * MM;

        const int q0 = lane;
        const float vx0 = cs[q0 * 3 + 0] - px;
        const float vy0 = cs[q0 * 3 + 1] - py;
        const float vz0 = cs[q0 * 3 + 2] - pz;
        const float d20 = vx0 * vx0 + vy0 * vy0 + vz0 * vz0;
        const float dist0 = sqrtf(d20);
        const bool adj0 = (q0 != j) && (dist0 < CUTOFF_F);
        drow[q0] = adj0 ? dist0 : 0.0f;
        const unsigned m0 = __ballot_sync(0xffffffffu, adj0);

        bool adj1 = false;
        const int q1 = lane + 32;
        float vx1 = 0.f, vy1 = 0.f, vz1 = 0.f, d21 = 0.f;
        if (lane < 16) {
            vx1 = cs[q1 * 3 + 0] - px;
            vy1 = cs[q1 * 3 + 1] - py;
            vz1 = cs[q1 * 3 + 2] - pz;
            d21 = vx1 * vx1 + vy1 * vy1 + vz1 * vz1;
            const float dist1 = sqrtf(d21);
            adj1 = (q1 != j) && (dist1 < CUTOFF_F);
            drow[q1] = adj1 ? dist1 : 0.0f;
        }
        const unsigned m1 = __ballot_sync(0xffffffffu, adj1);

        const int c0 = __popc(m0);
        if (adj0) {
            const int s = __popc(m0 & below);
            nx[rl][s] = vx0; ny[rl][s] = vy0; nz[rl][s] = vz0;
            nd2[rl][s] = d20; nk[rl][s] = q0;
        }
        if (adj1) {
            const int s = c0 + __popc(m1 & below);
            nx[rl][s] = vx1; ny[rl][s] = vy1; nz[rl][s] = vz1;
            nd2[rl][s] = d21; nk[rl][s] = q1;
        }
        if (lane == 0) cnts[rl] = c0 + __popc(m1);
    }
    __syncthreads();   // fill + neighbor data complete

    // Phase 2: both warp halves scatter interleaved triplets of row j.
    const int c  = cnts[rl];
    const int T  = c * c;
    const float fc = (float)c;
    #pragma unroll 3
    for (int g = lane + half * 32; g < T; g += 64) {
        const int pi = (int)__fdividef((float)g + 0.5f, fc);
        const int ki = g - pi * c;

        const float vix = nx[rl][pi], viy = ny[rl][pi], viz = nz[rl][pi];
        const float vkx = nx[rl][ki], vky = ny[rl][ki], vkz = nz[rl][ki];
        const float a  = vix * vkx + viy * vky + viz * vkz;
        const float b2 = fmaxf(nd2[rl][pi] * nd2[rl][ki] - a * a, 0.f);
        const float ang = fast_atan2_pos(sqrtf(b2), a);

        if (pi != ki)
            rowbase[nk[rl][pi] * MM + nk[rl][ki]] = ang;
    }
}

extern "C" void kernel_launch(void* const* d_in, const int* in_sizes, int n_in,
                              void* d_out, int out_size)
{
    const float* coords = (const float*)d_in[1];
    float* out = (float*)d_out;
    dimenet_kernel<<<CTAS, THREADS>>>(coords, out);
}